// round 13
// baseline (speedup 1.0000x reference)
#include <cuda_runtime.h>
#include <math.h>
#include <cstdint>

// Problem constants
constexpr int B_  = 2;
constexpr int S_  = 2048;
constexpr int D_  = 2048;
constexpr int H_  = 16;
constexpr int HD_ = 128;
constexpr size_t MAT = (size_t)B_ * S_ * D_;   // 8,388,608
constexpr size_t WSZ = (size_t)D_ * D_;        // 4,194,304
constexpr float SCL2E = 0.1275174053561348f;   // (1/sqrt(128)) * log2(e)

// Scratch (device globals: no allocation allowed)
__device__ float g_qt[MAT];     // rope'd q, scaled(log2e)+tf32, [B,H,S,HD]
__device__ float g_kr[MAT];     // rope'd k, tf32-rounded, [B,H,S,HD]
__device__ float g_vr[MAT];     // v, tf32-rounded, TRANSPOSED [B,H,HD,S]
__device__ float g_attn[MAT];   // attention output (tf32-rounded), [B,S,D]
__device__ float g_xt[MAT];     // x rounded to tf32
__device__ float g_wqt[WSZ];
__device__ float g_wkt[WSZ];
__device__ float g_wvt[WSZ];
__device__ float g_wot[WSZ];

// tcgen05 availability: only in the arch-specific (sm_103a / sm_100a) pass.
#if defined(__CUDA_ARCH__) && (defined(__CUDA_ARCH_FEAT_SM103_ALL) || defined(__CUDA_ARCH_FEAT_SM100_ALL) || defined(__CUDA_ARCH_FEAT_SM101_ALL))
#define TCOK 1
#else
#define TCOK 0
#endif

// ---------------------------------------------------------------------------
// Generic helpers
// ---------------------------------------------------------------------------
__device__ __forceinline__ uint32_t smem_u32(const void* p) {
    uint32_t a;
    asm("{ .reg .u64 t; cvta.to.shared.u64 t, %1; cvt.u32.u64 %0, t; }"
        : "=r"(a) : "l"(p));
    return a;
}
__device__ __forceinline__ float tf32r(float x) {
    uint32_t u; asm("cvt.rna.tf32.f32 %0, %1;" : "=r"(u) : "f"(x));
    return __uint_as_float(u);
}
__device__ __forceinline__ float ex2f(float x) {
    float r; asm("ex2.approx.f32 %0, %1;" : "=f"(r) : "f"(x));
    return r;
}
#define SWZ(o) ((o) ^ (((o) >> 3) & 0x70))

#if TCOK
__device__ __forceinline__ bool elect1() {
    uint32_t p;
    asm volatile("{ .reg .pred p; elect.sync _|p, 0xFFFFFFFF; selp.b32 %0, 1, 0, p; }"
                 : "=r"(p));
    return p != 0;
}

// K-major SW128 descriptor (LBO=1, SBO=64) — validated
constexpr uint64_t DESC_BASE =
    (uint64_t(2) << 61) | (uint64_t(1) << 46) | (uint64_t(64) << 32) | (uint64_t(1) << 16);
__device__ __forceinline__ uint64_t mk_desc(uint32_t a) {
    return DESC_BASE | ((uint64_t)(a >> 4) & 0x3FFF);
}

#define CP16(s, g) asm volatile("cp.async.cg.shared.global [%0], [%1], 16;" :: "r"(s), "l"(g))
#define CPCOMMIT() asm volatile("cp.async.commit_group;" ::: "memory")
#define CPWAIT1()  asm volatile("cp.async.wait_group 1;" ::: "memory")
#define CPWAIT2()  asm volatile("cp.async.wait_group 2;" ::: "memory")
#define FPA() asm volatile("fence.proxy.async.shared::cta;" ::: "memory")

#define MBINIT(addr, cnt) \
    asm volatile("mbarrier.init.shared.b64 [%0], %1;" :: "r"(addr), "r"(cnt) : "memory")

#define MBWAIT(mbar_smem_addr, phase_parity) do { \
    uint32_t _mbar = (uint32_t)(mbar_smem_addr); \
    uint32_t _parity = (uint32_t)(phase_parity); \
    uint32_t _done; \
    asm volatile( \
        "{\n\t.reg .pred p;\n\t" \
        "mbarrier.try_wait.parity.acquire.cta.shared::cta.b64 p, [%1], %2;\n\t" \
        "selp.b32 %0, 1, 0, p;\n\t}" \
        : "=r"(_done) : "r"(_mbar), "r"(_parity) : "memory"); \
    if (!_done) { \
        asm volatile( \
            "{\n\t.reg .pred P1;\n\t" \
            "WAIT_LOOP_%=:\n\t" \
            "mbarrier.try_wait.parity.acquire.cta.shared::cta.b64 P1, [%0], %1, 0x989680;\n\t" \
            "@P1 bra.uni WAIT_DONE_%=;\n\t" \
            "bra.uni WAIT_LOOP_%=;\n\t" \
            "WAIT_DONE_%=:\n\t}" \
            :: "r"(_mbar), "r"(_parity) : "memory"); \
    } \
} while(0)

// Arrive on cluster rank-0's mbarrier (same smem offset) from any CTA.
#define MBARR_RANK0(addr) \
    asm volatile( \
        "{\n\t.reg .b32 ra;\n\t" \
        "mapa.shared::cluster.u32 ra, %0, 0;\n\t" \
        "mbarrier.arrive.shared::cluster.b64 _, [ra];\n\t}" \
        :: "r"((uint32_t)(addr)) : "memory")

#define CLUSTER_SYNC() do { \
    asm volatile("barrier.cluster.arrive.aligned;" ::: "memory"); \
    asm volatile("barrier.cluster.wait.aligned;" ::: "memory"); \
} while(0)

#define TALLOC(sa, n) \
    asm volatile("tcgen05.alloc.cta_group::1.sync.aligned.shared::cta.b32 [%0], %1;" \
                 :: "r"(sa), "r"(n) : "memory")
#define TRELINQ() \
    asm volatile("tcgen05.relinquish_alloc_permit.cta_group::1.sync.aligned;")
#define TDEALLOC(t, n) \
    asm volatile("tcgen05.dealloc.cta_group::1.sync.aligned.b32 %0, %1;" :: "r"(t), "r"(n))
#define TCOMMIT(mb) \
    asm volatile("tcgen05.commit.cta_group::1.mbarrier::arrive::one.shared::cluster.b64 [%0];" \
                 :: "r"(mb) : "memory")

#define TALLOC2(sa, n) \
    asm volatile("tcgen05.alloc.cta_group::2.sync.aligned.shared::cta.b32 [%0], %1;" \
                 :: "r"(sa), "r"(n) : "memory")
#define TRELINQ2() \
    asm volatile("tcgen05.relinquish_alloc_permit.cta_group::2.sync.aligned;")
#define TDEALLOC2(t, n) \
    asm volatile("tcgen05.dealloc.cta_group::2.sync.aligned.b32 %0, %1;" :: "r"(t), "r"(n))
#define TCOMMIT2_MC(mb, mask) \
    asm volatile("tcgen05.commit.cta_group::2.mbarrier::arrive::one.shared::cluster.multicast::cluster.b64 [%0], %1;" \
                 :: "r"(mb), "h"((uint16_t)(mask)) : "memory")

#define TFENCE_AFTER()  asm volatile("tcgen05.fence::after_thread_sync;" ::: "memory")
#define TFENCE_BEFORE() asm volatile("tcgen05.fence::before_thread_sync;" ::: "memory")
#define TWAITLD() asm volatile("tcgen05.wait::ld.sync.aligned;" ::: "memory")

#define TLD32X32(r, tmem_addr) \
    asm volatile( \
        "tcgen05.ld.sync.aligned.32x32b.x32.b32 " \
        "{%0, %1, %2, %3, %4, %5, %6, %7, " \
        " %8, %9, %10, %11, %12, %13, %14, %15, " \
        " %16, %17, %18, %19, %20, %21, %22, %23, " \
        " %24, %25, %26, %27, %28, %29, %30, %31}, [%32];" \
        : "=r"((r)[0]),  "=r"((r)[1]),  "=r"((r)[2]),  "=r"((r)[3]), \
          "=r"((r)[4]),  "=r"((r)[5]),  "=r"((r)[6]),  "=r"((r)[7]), \
          "=r"((r)[8]),  "=r"((r)[9]),  "=r"((r)[10]), "=r"((r)[11]), \
          "=r"((r)[12]), "=r"((r)[13]), "=r"((r)[14]), "=r"((r)[15]), \
          "=r"((r)[16]), "=r"((r)[17]), "=r"((r)[18]), "=r"((r)[19]), \
          "=r"((r)[20]), "=r"((r)[21]), "=r"((r)[22]), "=r"((r)[23]), \
          "=r"((r)[24]), "=r"((r)[25]), "=r"((r)[26]), "=r"((r)[27]), \
          "=r"((r)[28]), "=r"((r)[29]), "=r"((r)[30]), "=r"((r)[31]) \
        : "r"(tmem_addr))

__device__ __forceinline__ void mma_tf32(uint32_t d, uint64_t ad, uint64_t bd,
                                         uint32_t idesc, bool acc) {
    uint32_t en = acc ? 1u : 0u;
    asm volatile(
        "{\n\t.reg .pred p;\n\tsetp.ne.u32 p, %4, 0;\n\t"
        "tcgen05.mma.cta_group::1.kind::tf32 [%0], %1, %2, %3, {%5, %5, %5, %5}, p;\n\t}"
        :: "r"(d), "l"(ad), "l"(bd), "r"(idesc), "r"(en), "r"(0u) : "memory");
}
__device__ __forceinline__ void mma_tf32_cg2(uint32_t d, uint64_t ad, uint64_t bd,
                                             uint32_t idesc, bool acc) {
    uint32_t en = acc ? 1u : 0u;
    asm volatile(
        "{\n\t.reg .pred p;\n\tsetp.ne.u32 p, %4, 0;\n\t"
        "tcgen05.mma.cta_group::2.kind::tf32 [%0], %1, %2, %3, "
        "{%5, %5, %5, %5, %5, %5, %5, %5}, p;\n\t}"
        :: "r"(d), "l"(ad), "l"(bd), "r"(idesc), "r"(en), "r"(0u) : "memory");
}
#endif  // TCOK

// ---------------------------------------------------------------------------
// Fused fp32 -> tf32 conversion for x + all 4 weights
// ---------------------------------------------------------------------------
__global__ __launch_bounds__(256) void conv_fused(
    const float* __restrict__ x,
    const float* __restrict__ wq, const float* __restrict__ wk,
    const float* __restrict__ wv, const float* __restrict__ wo,
    float* __restrict__ ox,
    float* __restrict__ oq, float* __restrict__ ok,
    float* __restrict__ ov, float* __restrict__ oo)
{
    const int i = blockIdx.x * 256 + threadIdx.x;
    const int NX = (int)(MAT / 4);
    const int NW = (int)(WSZ / 4);       // 2^20
    const float* src; float* dst; int off;
    if (i < NX) { src = x; dst = ox; off = i; }
    else {
        int j = i - NX;
        int w = j >> 20; off = j & (NW - 1);
        src = (w == 0) ? wq : (w == 1) ? wk : (w == 2) ? wv : wo;
        dst = (w == 0) ? oq : (w == 1) ? ok : (w == 2) ? ov : oo;
    }
    float4 v = ((const float4*)src)[off];
    v.x = tf32r(v.x); v.y = tf32r(v.y); v.z = tf32r(v.z); v.w = tf32r(v.w);
    ((float4*)dst)[off] = v;
}

// ---------------------------------------------------------------------------
// cg2 tf32 GEMM with FUSED RoPE/layout epilogue.
// Pair tile 256(M) x 512(N), grid (8, 16, nz), cluster (2,1,1).
// is_o = 1: plain C = A@W^T + bias into `oq` ([B,S,D]).
// is_o = 0: z = 0 (Q): rope -> *SCL2E -> tf32 -> oq [B,H,S,HD]
//           z = 1 (K): rope -> exact okt [B,H,S,HD] + tf32 okr [B,H,S,HD]
//           z = 2 (V): exact ovt [B,H,S,HD] + tf32 TRANSPOSED ovr [B,H,HD,S]
// ---------------------------------------------------------------------------
constexpr int CSTAGE = 49152;
constexpr int GEMM_SMEM = 3 * CSTAGE + 1024;   // 148,480
#if TCOK
constexpr uint32_t IDESC_CG2 =
    (16u << 24) | (32u << 17) | (1u << 4) | (2u << 7) | (2u << 10);
#endif

__global__ __launch_bounds__(128) void __cluster_dims__(2, 1, 1) gemm_cg2(
    const float* __restrict__ A,
    const float* __restrict__ W0, const float* __restrict__ W1,
    const float* __restrict__ W2,
    const float* __restrict__ b0, const float* __restrict__ b1,
    const float* __restrict__ b2,
    float* __restrict__ oq,
    float* __restrict__ okt, float* __restrict__ okr,
    float* __restrict__ ovt, float* __restrict__ ovr,
    const float* __restrict__ fc, const float* __restrict__ fs,
    int is_o)
{
    const int z = blockIdx.z;
    const float* W    = (z == 0) ? W0 : (z == 1) ? W1 : W2;
    const float* bias = (z == 0) ? b0 : (z == 1) ? b1 : b2;
    const int rank = blockIdx.x & 1;
    const int bn = (blockIdx.x >> 1) * 512;
    const int bm = blockIdx.y * 256;
#if TCOK
    extern __shared__ char dyn[];
    __shared__ uint64_t rdy[3];
    __shared__ uint64_t don[3];
    __shared__ uint32_t tptr[1];

    const int tid = threadIdx.x;
    const int wid = tid >> 5;
    const int lane = tid & 31;

    uint32_t dynb = (smem_u32(dyn) + 1023) & ~1023u;
    uint32_t rdb = smem_u32(rdy);
    uint32_t dnb = smem_u32(don);

    if (wid == 0) TALLOC2(smem_u32(tptr), 512);
    if (tid == 0) {
        for (int s = 0; s < 3; s++) { MBINIT(rdb + 8 * s, 2); MBINIT(dnb + 8 * s, 1); }
    }
    __syncthreads();
    CLUSTER_SYNC();
    const uint32_t tm = tptr[0];

    const int seg = tid & 7;
    const int rb  = tid >> 3;

    auto loadc = [&](int c) {
        const int kc = c * 32;
        const uint32_t st = dynb + (c % 3) * CSTAGE;
        const float* ga = A + (size_t)(bm + rank * 128 + rb) * 2048 + kc + seg * 4;
        const float* g0 = W + (size_t)(bn + rank * 128 + rb) * 2048 + kc + seg * 4;
        const float* g1 = W + (size_t)(bn + 256 + rank * 128 + rb) * 2048 + kc + seg * 4;
#pragma unroll
        for (int i = 0; i < 8; i++) {
            const uint32_t so = SWZ((rb + 16 * i) * 128 + seg * 16);
            CP16(st + so,         ga + (size_t)(16 * i) * 2048);
            CP16(st + 16384 + so, g0 + (size_t)(16 * i) * 2048);
            CP16(st + 32768 + so, g1 + (size_t)(16 * i) * 2048);
        }
    };

    loadc(0); CPCOMMIT();
    loadc(1); CPCOMMIT();

    for (int c = 0; c < 64; c++) {
        const int s = c % 3;
        CPWAIT1();
        __syncthreads();
        if (tid == 0) { FPA(); MBARR_RANK0(rdb + 8 * s); }
        if (rank == 0 && wid == 0 && elect1()) {
            MBWAIT(rdb + 8 * s, (c / 3) & 1);
            const uint32_t st = dynb + s * CSTAGE;
            const uint64_t ad = mk_desc(st);
            const uint64_t bd0 = mk_desc(st + 16384);
            const uint64_t bd1 = mk_desc(st + 32768);
#pragma unroll
            for (int k = 0; k < 4; k++) {
                mma_tf32_cg2(tm,       ad + 2 * k, bd0 + 2 * k, IDESC_CG2, (c | k) != 0);
                mma_tf32_cg2(tm + 256, ad + 2 * k, bd1 + 2 * k, IDESC_CG2, (c | k) != 0);
            }
            TCOMMIT2_MC(dnb + 8 * s, 0x3);
        }
        const int cn = c + 2;
        if (cn < 64) {
            if (c >= 1) MBWAIT(dnb + 8 * ((c - 1) % 3), ((c - 1) / 3) & 1);
            loadc(cn);
        }
        CPCOMMIT();
    }

    MBWAIT(dnb + 8 * (63 % 3), (63 / 3) & 1);
    TFENCE_AFTER();

    // Epilogue with fused transforms
    {
        const int grow = bm + rank * 128 + wid * 32 + lane;   // global A row
        const int b = grow >> 11;        // batch
        const int s = grow & 2047;       // seq pos
#pragma unroll
        for (int c0 = 0; c0 < 512; c0 += 32) {
            uint32_t r[32];
            TLD32X32(r, tm + c0);
            TWAITLD();
            if (is_o) {
                float* Crow = oq + (size_t)grow * 2048 + bn;
#pragma unroll
                for (int j4 = 0; j4 < 8; j4++) {
                    float4 o;
                    o.x = __uint_as_float(r[j4 * 4 + 0]) + __ldg(bias + bn + c0 + j4 * 4 + 0);
                    o.y = __uint_as_float(r[j4 * 4 + 1]) + __ldg(bias + bn + c0 + j4 * 4 + 1);
                    o.z = __uint_as_float(r[j4 * 4 + 2]) + __ldg(bias + bn + c0 + j4 * 4 + 2);
                    o.w = __uint_as_float(r[j4 * 4 + 3]) + __ldg(bias + bn + c0 + j4 * 4 + 3);
                    *(float4*)(Crow + c0 + j4 * 4) = o;
                }
            } else {
                const int colb = bn + c0;
                const int h = colb >> 7;
                const int hd0 = colb & 127;
                const size_t rbase = ((size_t)(b * H_ + h) * S_ + s) * HD_ + hd0;
#pragma unroll
                for (int j4 = 0; j4 < 8; j4++) {
                    float v0 = __uint_as_float(r[j4 * 4 + 0]) + __ldg(bias + colb + j4 * 4 + 0);
                    float v1 = __uint_as_float(r[j4 * 4 + 1]) + __ldg(bias + colb + j4 * 4 + 1);
                    float v2 = __uint_as_float(r[j4 * 4 + 2]) + __ldg(bias + colb + j4 * 4 + 2);
                    float v3 = __uint_as_float(r[j4 * 4 + 3]) + __ldg(bias + colb + j4 * 4 + 3);
                    if (z <= 1) {
                        const int p0 = (hd0 + j4 * 4) >> 1;
                        const float cf0 = __ldg(fc + s * 64 + p0);
                        const float sf0 = __ldg(fs + s * 64 + p0);
                        const float cf1 = __ldg(fc + s * 64 + p0 + 1);
                        const float sf1 = __ldg(fs + s * 64 + p0 + 1);
                        const float r0 = v0 * cf0 - v1 * sf0;
                        const float r1 = v0 * sf0 + v1 * cf0;
                        const float r2 = v2 * cf1 - v3 * sf1;
                        const float r3 = v2 * sf1 + v3 * cf1;
                        if (z == 0) {
                            float4 o = {tf32r(r0 * SCL2E), tf32r(r1 * SCL2E),
                                        tf32r(r2 * SCL2E), tf32r(r3 * SCL2E)};
                            *(float4*)(oq + rbase + j4 * 4) = o;
                        } else {
                            float4 e = {r0, r1, r2, r3};
                            *(float4*)(okt + rbase + j4 * 4) = e;
                            float4 t = {tf32r(r0), tf32r(r1), tf32r(r2), tf32r(r3)};
                            *(float4*)(okr + rbase + j4 * 4) = t;
                        }
                    } else {
                        float4 e = {v0, v1, v2, v3};
                        *(float4*)(ovt + rbase + j4 * 4) = e;
                        const size_t tb =
                            ((size_t)(b * H_ + h) * HD_ + hd0 + j4 * 4) * S_ + s;
                        ovr[tb]           = tf32r(v0);
                        ovr[tb + S_]      = tf32r(v1);
                        ovr[tb + 2 * S_]  = tf32r(v2);
                        ovr[tb + 3 * S_]  = tf32r(v3);
                    }
                }
            }
        }
    }
    __syncthreads();
    if (wid == 0) { TRELINQ2(); TDEALLOC2(tm, 512); }
    CLUSTER_SYNC();
#else
    // -------- SIMT fallback (plain-PTX pass only; never executes on GB300) --
    const int tid = threadIdx.x;
    const int row = bm + rank * 128 + tid;
    const int b = row >> 11, s = row & 2047;
    for (int col = bn; col < bn + 512; col += 2) {
        float a0 = 0.f, a1 = 0.f;
        for (int k = 0; k < 2048; k++) {
            const float a = A[(size_t)row * 2048 + k];
            a0 += a * W[(size_t)col * 2048 + k];
            a1 += a * W[(size_t)(col + 1) * 2048 + k];
        }
        a0 += bias[col]; a1 += bias[col + 1];
        if (is_o) {
            oq[(size_t)row * 2048 + col] = a0;
            oq[(size_t)row * 2048 + col + 1] = a1;
        } else {
            const int h = col >> 7, hd = col & 127, p = hd >> 1;
            const size_t rbase = ((size_t)(b * H_ + h) * S_ + s) * HD_ + hd;
            if (z <= 1) {
                const float cf = fc[s * 64 + p], sf = fs[s * 64 + p];
                const float r0 = a0 * cf - a1 * sf;
                const float r1 = a0 * sf + a1 * cf;
                if (z == 0) {
                    oq[rbase] = tf32r(r0 * SCL2E); oq[rbase + 1] = tf32r(r1 * SCL2E);
                } else {
                    okt[rbase] = r0;        okt[rbase + 1] = r1;
                    okr[rbase] = tf32r(r0); okr[rbase + 1] = tf32r(r1);
                }
            } else {
                ovt[rbase] = a0; ovt[rbase + 1] = a1;
                const size_t tb = ((size_t)(b * H_ + h) * HD_ + hd) * S_ + s;
                ovr[tb] = tf32r(a0); ovr[tb + S_] = tf32r(a1);
            }
        }
    }
#endif
}

// ---------------------------------------------------------------------------
// tcgen05 flash attention — unchanged from Round 11 (WIN).
// ---------------------------------------------------------------------------
constexpr int FL_SMEM = 229376 + 1024;  // Q 64K + K 2x32K + V 2x32K + P 32K
#if TCOK
constexpr uint32_t IDESC_S = (8u << 24) | (8u << 17)  | (1u << 4) | (2u << 7) | (2u << 10);
constexpr uint32_t IDESC_O = (8u << 24) | (16u << 17) | (1u << 4) | (2u << 7) | (2u << 10);

__device__ __forceinline__ void issueS(uint32_t d, uint32_t qb, uint32_t kb) {
#pragma unroll
    for (int c = 0; c < 4; c++) {
        uint64_t ad = mk_desc(qb + c * 16384);
        uint64_t bd = mk_desc(kb + c * 8192);
#pragma unroll
        for (int s = 0; s < 4; s++)
            mma_tf32(d, ad + 2 * s, bd + 2 * s, IDESC_S, (c | s) != 0);
    }
}
__device__ __forceinline__ void issuePV(uint32_t tO, uint32_t pb, uint32_t vb,
                                        bool first) {
#pragma unroll
    for (int c = 0; c < 2; c++) {
        uint64_t ad = mk_desc(pb + c * 16384);
        uint64_t bd = mk_desc(vb + c * 16384);
#pragma unroll
        for (int s = 0; s < 4; s++)
            mma_tf32(tO, ad + 2 * s, bd + 2 * s, IDESC_O,
                     !(first && c == 0 && s == 0));
    }
}
#endif

__global__ __launch_bounds__(256) void flash_tc(
    const float* __restrict__ Q, const float* __restrict__ K,
    const float* __restrict__ Vt, float* __restrict__ O)
{
#if TCOK
    extern __shared__ char fdyn[];
    __shared__ uint64_t fmb[3];
    __shared__ uint32_t ftp[1];
    __shared__ float lsh[256];

    const int tid = threadIdx.x;
    const int wid = tid >> 5;
    const int lane = tid & 31;
    const int bh = blockIdx.y;
    const int qt = (int)gridDim.x - 1 - (int)blockIdx.x;
    const int q0 = qt * 128;
    const int T = 2 * qt + 2;

    uint32_t base = (smem_u32(fdyn) + 1023) & ~1023u;
    const uint32_t qb = base;
    const uint32_t kst0 = base + 65536,  kst1 = base + 98304;
    const uint32_t vst0 = base + 131072, vst1 = base + 163840;
    const uint32_t pb = base + 196608;
    char* pgen = fdyn + (pb - smem_u32(fdyn));
    const uint32_t mbb = smem_u32(fmb);

    if (wid == 0) { TALLOC(smem_u32(ftp), 512); TRELINQ(); }
    if (tid == 0) { MBINIT(mbb, 1); MBINIT(mbb + 8, 1); MBINIT(mbb + 16, 1); }
    __syncthreads();
    const uint32_t tm  = ftp[0];
    const uint32_t tS0 = tm, tS1 = tm + 64, tO = tm + 128;

    const float* Qg  = Q  + ((size_t)bh * S_ + q0) * HD_;
    const float* Kg  = K  + (size_t)bh * S_ * HD_;
    const float* Vtg = Vt + (size_t)bh * HD_ * S_;

    const int rloc = (wid & 3) * 32 + lane;
    const int hc   = wid >> 2;
    const int wco  = hc * 32;

#pragma unroll
    for (int rep = 0; rep < 16; rep++) {
        int gid = rep * 256 + tid;
        int c = gid >> 10, rem = gid & 1023;
        int row = rem >> 3, seg = rem & 7;
        CP16(qb + c * 16384 + SWZ(row * 128 + seg * 16),
             Qg + (size_t)row * 128 + c * 32 + seg * 4);
    }
    auto loadK = [&](uint32_t st, int t) {
        const float* b0 = Kg + (size_t)t * 64 * 128;
#pragma unroll
        for (int rep = 0; rep < 8; rep++) {
            int gid = rep * 256 + tid;
            int c = gid >> 9, rem = gid & 511;
            int row = rem >> 3, seg = rem & 7;
            CP16(st + c * 8192 + SWZ(row * 128 + seg * 16),
                 b0 + (size_t)row * 128 + c * 32 + seg * 4);
        }
    };
    auto loadV = [&](uint32_t st, int t) {
        const float* b0 = Vtg + (size_t)t * 64;
#pragma unroll
        for (int rep = 0; rep < 8; rep++) {
            int gid = rep * 256 + tid;
            int c = gid >> 10, rem = gid & 1023;
            int row = rem >> 3, seg = rem & 7;
            CP16(st + c * 16384 + SWZ(row * 128 + seg * 16),
                 b0 + (size_t)row * S_ + c * 32 + seg * 4);
        }
    };
    loadK(kst0, 0); CPCOMMIT();
    loadK(kst1, 1); CPCOMMIT();
    loadV(vst0, 0); CPCOMMIT();
    CPWAIT2(); __syncthreads();
    if (wid == 0 && elect1()) {
        FPA();
        issueS(tS0, qb, kst0);
        TCOMMIT(mbb + 0);
    }

    float l = 0.f;
    int sph0 = 0, sph1 = 0, pvph = 0;

    for (int t = 0; t < T; t++) {
        const int buf = t & 1;
        if (buf == 0) { MBWAIT(mbb + 0, sph0); sph0 ^= 1; }
        else          { MBWAIT(mbb + 8, sph1); sph1 ^= 1; }
        if (t + 2 < T) loadK(buf ? kst1 : kst0, t + 2);
        CPCOMMIT();
        TFENCE_AFTER();
        uint32_t sr[32];
        TLD32X32(sr, (buf ? tS1 : tS0) + wco);
        TWAITLD();
        TFENCE_BEFORE();
        CPWAIT2(); __syncthreads();
        if (t + 1 < T && wid == 0 && elect1()) {
            FPA();
            issueS(buf ? tS0 : tS1, qb, ((t + 1) & 1) ? kst1 : kst0);
            TCOMMIT(mbb + 8 * ((t + 1) & 1));
        }
        const int lim = q0 + rloc - 64 * t - wco;
        float pf[32];
#pragma unroll
        for (int c = 0; c < 32; c++) {
            float e = (c <= lim) ? ex2f(__uint_as_float(sr[c])) : 0.f;
            l += e;
            pf[c] = tf32r(e);
        }
        if (t > 0) { MBWAIT(mbb + 16, pvph); pvph ^= 1; }
        if (t + 1 < T) loadV(((t + 1) & 1) ? vst1 : vst0, t + 1);
        CPCOMMIT();
        CPWAIT2();
#pragma unroll
        for (int seg = 0; seg < 8; seg++) {
            float4 w4 = {pf[seg * 4 + 0], pf[seg * 4 + 1],
                         pf[seg * 4 + 2], pf[seg * 4 + 3]};
            *(float4*)(pgen + hc * 16384 + SWZ(rloc * 128 + seg * 16)) = w4;
        }
        __syncthreads();
        if (wid == 0 && elect1()) {
            FPA();
            issuePV(tO, pb, buf ? vst1 : vst0, t == 0);
            TCOMMIT(mbb + 16);
        }
    }
    lsh[tid] = l;
    MBWAIT(mbb + 16, pvph);
    TFENCE_AFTER();
    __syncthreads();
    const float inv = 1.f / (lsh[tid] + lsh[tid ^ 128]);
    uint32_t orr[64];
    TLD32X32(orr,      tO + hc * 64);
    TLD32X32(orr + 32, tO + hc * 64 + 32);
    TWAITLD();
    const int b = bh >> 4, h = bh & 15;
    float* Og = O + ((size_t)(b * S_ + q0 + rloc)) * D_ + h * HD_ + hc * 64;
#pragma unroll
    for (int j = 0; j < 16; j++) {
        float4 o;
        o.x = tf32r(__uint_as_float(orr[4 * j + 0]) * inv);
        o.y = tf32r(__uint_as_float(orr[4 * j + 1]) * inv);
        o.z = tf32r(__uint_as_float(orr[4 * j + 2]) * inv);
        o.w = tf32r(__uint_as_float(orr[4 * j + 3]) * inv);
        *(float4*)(Og + 4 * j) = o;
    }
    __syncthreads();
    if (wid == 0) TDEALLOC(tm, 512);
#else
    // -------- naive correct fallback (plain-PTX pass only) --------
    const int bh = blockIdx.y;
    const int qt = (int)gridDim.x - 1 - (int)blockIdx.x;
    const int q0 = qt * 128;
    const int b = bh >> 4, h = bh & 15;
    if (threadIdx.x >= 128) return;
    const int r = q0 + threadIdx.x;
    const float* Qr = Q + ((size_t)bh * S_ + r) * HD_;
    const float* Kb = K + (size_t)bh * S_ * HD_;
    const float* Vb = Vt + (size_t)bh * HD_ * S_;
    float o[HD_];
    for (int c = 0; c < HD_; c++) o[c] = 0.f;
    float l = 0.f;
    for (int kk = 0; kk <= r; kk++) {
        float s = 0.f;
        for (int c = 0; c < HD_; c++) s += Qr[c] * Kb[(size_t)kk * HD_ + c];
        float e = exp2f(s);
        l += e;
        for (int c = 0; c < HD_; c++) o[c] += e * Vb[(size_t)c * S_ + kk];
    }
    const float inv = 1.f / l;
    float* Og = O + ((size_t)(b * S_ + r)) * D_ + h * HD_;
    for (int c = 0; c < HD_; c++) Og[c] = tf32r(o[c] * inv);
#endif
}

// ---------------------------------------------------------------------------
// Launch
// ---------------------------------------------------------------------------
extern "C" void kernel_launch(void* const* d_in, const int* in_sizes, int n_in,
                              void* d_out, int out_size)
{
    const float* x   = (const float*)d_in[0];
    const float* wq  = (const float*)d_in[1];
    const float* wqb = (const float*)d_in[2];
    const float* wk  = (const float*)d_in[3];
    const float* wkb = (const float*)d_in[4];
    const float* wv  = (const float*)d_in[5];
    const float* wvb = (const float*)d_in[6];
    const float* wo  = (const float*)d_in[7];
    const float* wob = (const float*)d_in[8];
    const float* fc  = (const float*)d_in[9];
    const float* fs  = (const float*)d_in[10];

    float* out   = (float*)d_out;
    float* out_k = out + MAT;
    float* out_v = out_k + MAT;

    float *gqt, *gkr, *gvr, *gattn, *gxt, *gwqt, *gwkt, *gwvt, *gwot;
    cudaGetSymbolAddress((void**)&gqt,   g_qt);
    cudaGetSymbolAddress((void**)&gkr,   g_kr);
    cudaGetSymbolAddress((void**)&gvr,   g_vr);
    cudaGetSymbolAddress((void**)&gattn, g_attn);
    cudaGetSymbolAddress((void**)&gxt,   g_xt);
    cudaGetSymbolAddress((void**)&gwqt,  g_wqt);
    cudaGetSymbolAddress((void**)&gwkt,  g_wkt);
    cudaGetSymbolAddress((void**)&gwvt,  g_wvt);
    cudaGetSymbolAddress((void**)&gwot,  g_wot);

    const int NCONV = (int)((MAT + 4 * WSZ) / 4 / 256);
    conv_fused<<<NCONV, 256>>>(x, wq, wk, wv, wo, gxt, gwqt, gwkt, gwvt, gwot);

    cudaFuncSetAttribute(gemm_cg2,
                         cudaFuncAttributeMaxDynamicSharedMemorySize, GEMM_SMEM);

    // Fused QKV projection + RoPE + layout transforms
    gemm_cg2<<<dim3(8, 16, 3), 128, GEMM_SMEM>>>(
        gxt, gwqt, gwkt, gwvt, wqb, wkb, wvb,
        gqt, out_k, gkr, out_v, gvr, fc, fs, 0);

    cudaFuncSetAttribute(flash_tc,
                         cudaFuncAttributeMaxDynamicSharedMemorySize, FL_SMEM);
    flash_tc<<<dim3(16, B_ * H_), 256, FL_SMEM>>>(gqt, gkr, gvr, gattn);

    // O projection (plain epilogue)
    gemm_cg2<<<dim3(8, 16, 1), 128, GEMM_SMEM>>>(
        gattn, gwot, gwot, gwot, wob, wob, wob,
        out, out_k, gkr, out_v, gvr, fc, fs, 1);
}

// round 17
// speedup vs baseline: 1.4990x; 1.4990x over previous
#include <cuda_runtime.h>
#include <cuda_fp16.h>
#include <math.h>
#include <cstdint>

// Problem constants
constexpr int B_  = 2;
constexpr int S_  = 2048;
constexpr int D_  = 2048;
constexpr int H_  = 16;
constexpr int HD_ = 128;
constexpr size_t MAT = (size_t)B_ * S_ * D_;   // 8,388,608
constexpr size_t WSZ = (size_t)D_ * D_;        // 4,194,304
constexpr float SCL2E = 0.1275174053561348f;   // (1/sqrt(128)) * log2(e)

// Scratch (device globals: no allocation allowed)
__device__ float  g_q[MAT];      // q projection [B,S,D] (fp32)
__device__ float  g_k[MAT];      // k projection [B,S,D]
__device__ float  g_v[MAT];      // v projection [B,S,D]
__device__ float  g_qt[MAT];     // rope'd q, scaled(log2e)+tf32, [B,H,S,HD]
__device__ float  g_kr[MAT];     // rope'd k, tf32-rounded, [B,H,S,HD]
__device__ float  g_vr[MAT];     // v, tf32-rounded, TRANSPOSED [B,H,HD,S]
__device__ __half g_attnh[MAT];  // attention output (fp16), [B,S,D]
__device__ __half g_xh[MAT];     // x in fp16
__device__ __half g_wqh[WSZ];
__device__ __half g_wkh[WSZ];
__device__ __half g_wvh[WSZ];
__device__ __half g_woh[WSZ];

// tcgen05 availability: only in the arch-specific (sm_103a / sm_100a) pass.
#if defined(__CUDA_ARCH__) && (defined(__CUDA_ARCH_FEAT_SM103_ALL) || defined(__CUDA_ARCH_FEAT_SM100_ALL) || defined(__CUDA_ARCH_FEAT_SM101_ALL))
#define TCOK 1
#else
#define TCOK 0
#endif

// ---------------------------------------------------------------------------
// Generic helpers
// ---------------------------------------------------------------------------
__device__ __forceinline__ uint32_t smem_u32(const void* p) {
    uint32_t a;
    asm("{ .reg .u64 t; cvta.to.shared.u64 t, %1; cvt.u32.u64 %0, t; }"
        : "=r"(a) : "l"(p));
    return a;
}
__device__ __forceinline__ float tf32r(float x) {
    uint32_t u; asm("cvt.rna.tf32.f32 %0, %1;" : "=r"(u) : "f"(x));
    return __uint_as_float(u);
}
__device__ __forceinline__ float ex2f(float x) {
    float r; asm("ex2.approx.f32 %0, %1;" : "=f"(r) : "f"(x));
    return r;
}
#define SWZ(o) ((o) ^ (((o) >> 3) & 0x70))

#if TCOK
__device__ __forceinline__ bool elect1() {
    uint32_t p;
    asm volatile("{ .reg .pred p; elect.sync _|p, 0xFFFFFFFF; selp.b32 %0, 1, 0, p; }"
                 : "=r"(p));
    return p != 0;
}

// K-major SW128 descriptor (LBO=1, SBO=64) — validated
constexpr uint64_t DESC_BASE =
    (uint64_t(2) << 61) | (uint64_t(1) << 46) | (uint64_t(64) << 32) | (uint64_t(1) << 16);
__device__ __forceinline__ uint64_t mk_desc(uint32_t a) {
    return DESC_BASE | ((uint64_t)(a >> 4) & 0x3FFF);
}

#define CP16(s, g) asm volatile("cp.async.cg.shared.global [%0], [%1], 16;" :: "r"(s), "l"(g))
#define CPCOMMIT() asm volatile("cp.async.commit_group;" ::: "memory")
#define CPWAIT1()  asm volatile("cp.async.wait_group 1;" ::: "memory")
#define CPWAIT2()  asm volatile("cp.async.wait_group 2;" ::: "memory")
#define FPA() asm volatile("fence.proxy.async.shared::cta;" ::: "memory")

#define MBINIT(addr, cnt) \
    asm volatile("mbarrier.init.shared.b64 [%0], %1;" :: "r"(addr), "r"(cnt) : "memory")

#define MBWAIT(mbar_smem_addr, phase_parity) do { \
    uint32_t _mbar = (uint32_t)(mbar_smem_addr); \
    uint32_t _parity = (uint32_t)(phase_parity); \
    uint32_t _done; \
    asm volatile( \
        "{\n\t.reg .pred p;\n\t" \
        "mbarrier.try_wait.parity.acquire.cta.shared::cta.b64 p, [%1], %2;\n\t" \
        "selp.b32 %0, 1, 0, p;\n\t}" \
        : "=r"(_done) : "r"(_mbar), "r"(_parity) : "memory"); \
    if (!_done) { \
        asm volatile( \
            "{\n\t.reg .pred P1;\n\t" \
            "WAIT_LOOP_%=:\n\t" \
            "mbarrier.try_wait.parity.acquire.cta.shared::cta.b64 P1, [%0], %1, 0x989680;\n\t" \
            "@P1 bra.uni WAIT_DONE_%=;\n\t" \
            "bra.uni WAIT_LOOP_%=;\n\t" \
            "WAIT_DONE_%=:\n\t}" \
            :: "r"(_mbar), "r"(_parity) : "memory"); \
    } \
} while(0)

// Arrive on cluster rank-0's mbarrier (same smem offset) from any CTA.
#define MBARR_RANK0(addr) \
    asm volatile( \
        "{\n\t.reg .b32 ra;\n\t" \
        "mapa.shared::cluster.u32 ra, %0, 0;\n\t" \
        "mbarrier.arrive.shared::cluster.b64 _, [ra];\n\t}" \
        :: "r"((uint32_t)(addr)) : "memory")

#define CLUSTER_SYNC() do { \
    asm volatile("barrier.cluster.arrive.aligned;" ::: "memory"); \
    asm volatile("barrier.cluster.wait.aligned;" ::: "memory"); \
} while(0)

#define TALLOC(sa, n) \
    asm volatile("tcgen05.alloc.cta_group::1.sync.aligned.shared::cta.b32 [%0], %1;" \
                 :: "r"(sa), "r"(n) : "memory")
#define TRELINQ() \
    asm volatile("tcgen05.relinquish_alloc_permit.cta_group::1.sync.aligned;")
#define TDEALLOC(t, n) \
    asm volatile("tcgen05.dealloc.cta_group::1.sync.aligned.b32 %0, %1;" :: "r"(t), "r"(n))
#define TCOMMIT(mb) \
    asm volatile("tcgen05.commit.cta_group::1.mbarrier::arrive::one.shared::cluster.b64 [%0];" \
                 :: "r"(mb) : "memory")

#define TALLOC2(sa, n) \
    asm volatile("tcgen05.alloc.cta_group::2.sync.aligned.shared::cta.b32 [%0], %1;" \
                 :: "r"(sa), "r"(n) : "memory")
#define TRELINQ2() \
    asm volatile("tcgen05.relinquish_alloc_permit.cta_group::2.sync.aligned;")
#define TDEALLOC2(t, n) \
    asm volatile("tcgen05.dealloc.cta_group::2.sync.aligned.b32 %0, %1;" :: "r"(t), "r"(n))
#define TCOMMIT2_MC(mb, mask) \
    asm volatile("tcgen05.commit.cta_group::2.mbarrier::arrive::one.shared::cluster.multicast::cluster.b64 [%0], %1;" \
                 :: "r"(mb), "h"((uint16_t)(mask)) : "memory")

#define TFENCE_AFTER()  asm volatile("tcgen05.fence::after_thread_sync;" ::: "memory")
#define TFENCE_BEFORE() asm volatile("tcgen05.fence::before_thread_sync;" ::: "memory")
#define TWAITLD() asm volatile("tcgen05.wait::ld.sync.aligned;" ::: "memory")

#define TLD32X32(r, tmem_addr) \
    asm volatile( \
        "tcgen05.ld.sync.aligned.32x32b.x32.b32 " \
        "{%0, %1, %2, %3, %4, %5, %6, %7, " \
        " %8, %9, %10, %11, %12, %13, %14, %15, " \
        " %16, %17, %18, %19, %20, %21, %22, %23, " \
        " %24, %25, %26, %27, %28, %29, %30, %31}, [%32];" \
        : "=r"((r)[0]),  "=r"((r)[1]),  "=r"((r)[2]),  "=r"((r)[3]), \
          "=r"((r)[4]),  "=r"((r)[5]),  "=r"((r)[6]),  "=r"((r)[7]), \
          "=r"((r)[8]),  "=r"((r)[9]),  "=r"((r)[10]), "=r"((r)[11]), \
          "=r"((r)[12]), "=r"((r)[13]), "=r"((r)[14]), "=r"((r)[15]), \
          "=r"((r)[16]), "=r"((r)[17]), "=r"((r)[18]), "=r"((r)[19]), \
          "=r"((r)[20]), "=r"((r)[21]), "=r"((r)[22]), "=r"((r)[23]), \
          "=r"((r)[24]), "=r"((r)[25]), "=r"((r)[26]), "=r"((r)[27]), \
          "=r"((r)[28]), "=r"((r)[29]), "=r"((r)[30]), "=r"((r)[31]) \
        : "r"(tmem_addr))

__device__ __forceinline__ void mma_tf32(uint32_t d, uint64_t ad, uint64_t bd,
                                         uint32_t idesc, bool acc) {
    uint32_t en = acc ? 1u : 0u;
    asm volatile(
        "{\n\t.reg .pred p;\n\tsetp.ne.u32 p, %4, 0;\n\t"
        "tcgen05.mma.cta_group::1.kind::tf32 [%0], %1, %2, %3, {%5, %5, %5, %5}, p;\n\t}"
        :: "r"(d), "l"(ad), "l"(bd), "r"(idesc), "r"(en), "r"(0u) : "memory");
}
__device__ __forceinline__ void mma_f16_cg2(uint32_t d, uint64_t ad, uint64_t bd,
                                            uint32_t idesc, bool acc) {
    uint32_t en = acc ? 1u : 0u;
    asm volatile(
        "{\n\t.reg .pred p;\n\tsetp.ne.u32 p, %4, 0;\n\t"
        "tcgen05.mma.cta_group::2.kind::f16 [%0], %1, %2, %3, "
        "{%5, %5, %5, %5, %5, %5, %5, %5}, p;\n\t}"
        :: "r"(d), "l"(ad), "l"(bd), "r"(idesc), "r"(en), "r"(0u) : "memory");
}
#endif  // TCOK

// ---------------------------------------------------------------------------
// Fused fp32 -> fp16 conversion for x + all 4 weights
// ---------------------------------------------------------------------------
__global__ __launch_bounds__(256) void conv_fused(
    const float* __restrict__ x,
    const float* __restrict__ wq, const float* __restrict__ wk,
    const float* __restrict__ wv, const float* __restrict__ wo,
    __half* __restrict__ ox,
    __half* __restrict__ oq, __half* __restrict__ ok,
    __half* __restrict__ ov, __half* __restrict__ oo)
{
    const int i = blockIdx.x * 256 + threadIdx.x;
    const int NX = (int)(MAT / 4);
    const int NW = (int)(WSZ / 4);       // 2^20
    const float* src; __half* dst; int off;
    if (i < NX) { src = x; dst = ox; off = i; }
    else {
        int j = i - NX;
        int w = j >> 20; off = j & (NW - 1);
        src = (w == 0) ? wq : (w == 1) ? wk : (w == 2) ? wv : wo;
        dst = (w == 0) ? oq : (w == 1) ? ok : (w == 2) ? ov : oo;
    }
    float4 v = ((const float4*)src)[off];
    __half2 h0 = __floats2half2_rn(v.x, v.y);
    __half2 h1 = __floats2half2_rn(v.z, v.w);
    uint2 pk = {*(uint32_t*)&h0, *(uint32_t*)&h1};
    ((uint2*)dst)[off] = pk;
}

// ---------------------------------------------------------------------------
// cg2 fp16 GEMM: pair tile 256(M) x 512(N), grid (8, 16, nz), cluster (2,1,1).
// K-chunk = 64 halfs (128B rows, SW128), 32 chunks, K=16 per MMA step.
// Epilogue: fp32 TMEM + bias -> fp32 C (R11-style plain epilogue).
// ---------------------------------------------------------------------------
constexpr int CSTAGE = 49152;
constexpr int GEMM_SMEM = 3 * CSTAGE + 1024;   // 148,480
#if TCOK
// kind::f16: dtype F32 (1<<4), atype/btype F16 (0), N=256 (32<<17), M=256 (16<<24)
constexpr uint32_t IDESC_F16_CG2 = (16u << 24) | (32u << 17) | (1u << 4);
#endif

__global__ __launch_bounds__(128) void __cluster_dims__(2, 1, 1) gemm_cg2(
    const __half* __restrict__ A,
    const __half* __restrict__ W0, const __half* __restrict__ W1,
    const __half* __restrict__ W2,
    const float* __restrict__ b0, const float* __restrict__ b1,
    const float* __restrict__ b2,
    float* __restrict__ C0, float* __restrict__ C1, float* __restrict__ C2)
{
    const int z = blockIdx.z;
    const __half* W   = (z == 0) ? W0 : (z == 1) ? W1 : W2;
    const float* bias = (z == 0) ? b0 : (z == 1) ? b1 : b2;
    float* C          = (z == 0) ? C0 : (z == 1) ? C1 : C2;
    const int rank = blockIdx.x & 1;
    const int bn = (blockIdx.x >> 1) * 512;
    const int bm = blockIdx.y * 256;
#if TCOK
    extern __shared__ char dyn[];
    __shared__ uint64_t rdy[3];
    __shared__ uint64_t don[3];
    __shared__ uint32_t tptr[1];

    const int tid = threadIdx.x;
    const int wid = tid >> 5;
    const int lane = tid & 31;

    uint32_t dynb = (smem_u32(dyn) + 1023) & ~1023u;
    uint32_t rdb = smem_u32(rdy);
    uint32_t dnb = smem_u32(don);

    if (wid == 0) TALLOC2(smem_u32(tptr), 512);
    if (tid == 0) {
        for (int s = 0; s < 3; s++) { MBINIT(rdb + 8 * s, 2); MBINIT(dnb + 8 * s, 1); }
    }
    __syncthreads();
    CLUSTER_SYNC();
    const uint32_t tm = tptr[0];

    const int seg = tid & 7;       // 16B (= 8 halfs) segment in 128B row
    const int rb  = tid >> 3;      // 0..15

    // K-chunk c covers halfs [c*64, c*64+64)
    auto loadc = [&](int c) {
        const int kc = c * 64;
        const uint32_t st = dynb + (c % 3) * CSTAGE;
        const __half* ga = A + (size_t)(bm + rank * 128 + rb) * 2048 + kc + seg * 8;
        const __half* g0 = W + (size_t)(bn + rank * 128 + rb) * 2048 + kc + seg * 8;
        const __half* g1 = W + (size_t)(bn + 256 + rank * 128 + rb) * 2048 + kc + seg * 8;
#pragma unroll
        for (int i = 0; i < 8; i++) {
            const uint32_t so = SWZ((rb + 16 * i) * 128 + seg * 16);
            CP16(st + so,         ga + (size_t)(16 * i) * 2048);
            CP16(st + 16384 + so, g0 + (size_t)(16 * i) * 2048);
            CP16(st + 32768 + so, g1 + (size_t)(16 * i) * 2048);
        }
    };

    loadc(0); CPCOMMIT();
    loadc(1); CPCOMMIT();

    for (int c = 0; c < 32; c++) {
        const int s = c % 3;
        CPWAIT1();
        __syncthreads();
        if (tid == 0) { FPA(); MBARR_RANK0(rdb + 8 * s); }
        if (rank == 0 && wid == 0 && elect1()) {
            MBWAIT(rdb + 8 * s, (c / 3) & 1);
            const uint32_t st = dynb + s * CSTAGE;
            const uint64_t ad = mk_desc(st);
            const uint64_t bd0 = mk_desc(st + 16384);
            const uint64_t bd1 = mk_desc(st + 32768);
#pragma unroll
            for (int k = 0; k < 4; k++) {   // 4 steps of K=16 halfs (32B = 2 units)
                mma_f16_cg2(tm,       ad + 2 * k, bd0 + 2 * k, IDESC_F16_CG2, (c | k) != 0);
                mma_f16_cg2(tm + 256, ad + 2 * k, bd1 + 2 * k, IDESC_F16_CG2, (c | k) != 0);
            }
            TCOMMIT2_MC(dnb + 8 * s, 0x3);
        }
        const int cn = c + 2;
        if (cn < 32) {
            if (c >= 1) MBWAIT(dnb + 8 * ((c - 1) % 3), ((c - 1) / 3) & 1);
            loadc(cn);
        }
        CPCOMMIT();
    }

    MBWAIT(dnb + 8 * (31 % 3), (31 / 3) & 1);
    TFENCE_AFTER();

    {
        const int grow = bm + rank * 128 + wid * 32 + lane;
        float* Crow = C + (size_t)grow * 2048 + bn;
#pragma unroll
        for (int c0 = 0; c0 < 512; c0 += 32) {
            uint32_t r[32];
            TLD32X32(r, tm + c0);
            TWAITLD();
#pragma unroll
            for (int j4 = 0; j4 < 8; j4++) {
                float4 o;
                o.x = __uint_as_float(r[j4 * 4 + 0]) + __ldg(bias + bn + c0 + j4 * 4 + 0);
                o.y = __uint_as_float(r[j4 * 4 + 1]) + __ldg(bias + bn + c0 + j4 * 4 + 1);
                o.z = __uint_as_float(r[j4 * 4 + 2]) + __ldg(bias + bn + c0 + j4 * 4 + 2);
                o.w = __uint_as_float(r[j4 * 4 + 3]) + __ldg(bias + bn + c0 + j4 * 4 + 3);
                *(float4*)(Crow + c0 + j4 * 4) = o;
            }
        }
    }
    __syncthreads();
    if (wid == 0) { TRELINQ2(); TDEALLOC2(tm, 512); }
    CLUSTER_SYNC();
#else
    // -------- SIMT fallback (plain-PTX pass only; never executes on GB300) --
    const int tid = threadIdx.x;
    const int row = bm + rank * 128 + tid;
    for (int nc = 0; nc < 8; nc++) {
        float acc[64];
#pragma unroll
        for (int j = 0; j < 64; j++) acc[j] = 0.f;
        for (int k = 0; k < 2048; k++) {
            const float a = __half2float(A[(size_t)row * 2048 + k]);
            for (int j = 0; j < 64; j++)
                acc[j] += a * __half2float(W[(size_t)(bn + nc * 64 + j) * 2048 + k]);
        }
        for (int j = 0; j < 64; j++)
            C[(size_t)row * 2048 + bn + nc * 64 + j] = acc[j] + bias[bn + nc * 64 + j];
    }
#endif
}

// ---------------------------------------------------------------------------
// RoPE + transpose (R11-exact). qt pre-scaled by SCALE*log2(e).
// ---------------------------------------------------------------------------
__global__ __launch_bounds__(256) void rope_transpose(
    const float* __restrict__ q, const float* __restrict__ k,
    const float* __restrict__ v,
    const float* __restrict__ fc, const float* __restrict__ fs,
    float* __restrict__ qt, float* __restrict__ kt, float* __restrict__ vt,
    float* __restrict__ kr, float* __restrict__ vr)
{
    const int bs = blockIdx.x;
    const int s = bs % S_;
    const int b = bs / S_;
    const float* qr = q + (size_t)bs * D_;
    const float* krow = k + (size_t)bs * D_;
    const float* vrow = v + (size_t)bs * D_;

    for (int idx = threadIdx.x; idx < D_ / 2; idx += 256) {
        const int h = idx >> 6;
        const int p = idx & 63;
        const float c  = fc[s * 64 + p];
        const float sn = fs[s * 64 + p];
        const size_t dst = ((size_t)(b * H_ + h) * S_ + s) * HD_ + 2 * p;
        const int srcoff = h * HD_ + 2 * p;
        {
            float tr = qr[srcoff], ti = qr[srcoff + 1];
            qt[dst]     = tf32r((tr * c - ti * sn) * SCL2E);
            qt[dst + 1] = tf32r((tr * sn + ti * c) * SCL2E);
        }
        {
            float tr = krow[srcoff], ti = krow[srcoff + 1];
            float k0 = tr * c - ti * sn, k1 = tr * sn + ti * c;
            kt[dst] = k0;         kt[dst + 1] = k1;
            kr[dst] = tf32r(k0);  kr[dst + 1] = tf32r(k1);
        }
        {
            float v0 = vrow[srcoff], v1 = vrow[srcoff + 1];
            vt[dst] = v0;  vt[dst + 1] = v1;
            const size_t tb = ((size_t)(b * H_ + h) * HD_ + 2 * p) * S_ + s;
            vr[tb]      = tf32r(v0);
            vr[tb + S_] = tf32r(v1);
        }
    }
}

// ---------------------------------------------------------------------------
// tcgen05 flash attention — R11-exact except epilogue writes fp16 attn.
// ---------------------------------------------------------------------------
constexpr int FL_SMEM = 229376 + 1024;  // Q 64K + K 2x32K + V 2x32K + P 32K
#if TCOK
constexpr uint32_t IDESC_S = (8u << 24) | (8u << 17)  | (1u << 4) | (2u << 7) | (2u << 10);
constexpr uint32_t IDESC_O = (8u << 24) | (16u << 17) | (1u << 4) | (2u << 7) | (2u << 10);

__device__ __forceinline__ void issueS(uint32_t d, uint32_t qb, uint32_t kb) {
#pragma unroll
    for (int c = 0; c < 4; c++) {
        uint64_t ad = mk_desc(qb + c * 16384);
        uint64_t bd = mk_desc(kb + c * 8192);
#pragma unroll
        for (int s = 0; s < 4; s++)
            mma_tf32(d, ad + 2 * s, bd + 2 * s, IDESC_S, (c | s) != 0);
    }
}
__device__ __forceinline__ void issuePV(uint32_t tO, uint32_t pb, uint32_t vb,
                                        bool first) {
#pragma unroll
    for (int c = 0; c < 2; c++) {
        uint64_t ad = mk_desc(pb + c * 16384);
        uint64_t bd = mk_desc(vb + c * 16384);
#pragma unroll
        for (int s = 0; s < 4; s++)
            mma_tf32(tO, ad + 2 * s, bd + 2 * s, IDESC_O,
                     !(first && c == 0 && s == 0));
    }
}
#endif

__global__ __launch_bounds__(256) void flash_tc(
    const float* __restrict__ Q, const float* __restrict__ K,
    const float* __restrict__ Vt, __half* __restrict__ O)
{
#if TCOK
    extern __shared__ char fdyn[];
    __shared__ uint64_t fmb[3];
    __shared__ uint32_t ftp[1];
    __shared__ float lsh[256];

    const int tid = threadIdx.x;
    const int wid = tid >> 5;
    const int lane = tid & 31;
    const int bh = blockIdx.y;
    const int qt = (int)gridDim.x - 1 - (int)blockIdx.x;
    const int q0 = qt * 128;
    const int T = 2 * qt + 2;

    uint32_t base = (smem_u32(fdyn) + 1023) & ~1023u;
    const uint32_t qb = base;
    const uint32_t kst0 = base + 65536,  kst1 = base + 98304;
    const uint32_t vst0 = base + 131072, vst1 = base + 163840;
    const uint32_t pb = base + 196608;
    char* pgen = fdyn + (pb - smem_u32(fdyn));
    const uint32_t mbb = smem_u32(fmb);

    if (wid == 0) { TALLOC(smem_u32(ftp), 512); TRELINQ(); }
    if (tid == 0) { MBINIT(mbb, 1); MBINIT(mbb + 8, 1); MBINIT(mbb + 16, 1); }
    __syncthreads();
    const uint32_t tm  = ftp[0];
    const uint32_t tS0 = tm, tS1 = tm + 64, tO = tm + 128;

    const float* Qg  = Q  + ((size_t)bh * S_ + q0) * HD_;
    const float* Kg  = K  + (size_t)bh * S_ * HD_;
    const float* Vtg = Vt + (size_t)bh * HD_ * S_;

    const int rloc = (wid & 3) * 32 + lane;
    const int hc   = wid >> 2;
    const int wco  = hc * 32;

#pragma unroll
    for (int rep = 0; rep < 16; rep++) {
        int gid = rep * 256 + tid;
        int c = gid >> 10, rem = gid & 1023;
        int row = rem >> 3, seg = rem & 7;
        CP16(qb + c * 16384 + SWZ(row * 128 + seg * 16),
             Qg + (size_t)row * 128 + c * 32 + seg * 4);
    }
    auto loadK = [&](uint32_t st, int t) {
        const float* b0 = Kg + (size_t)t * 64 * 128;
#pragma unroll
        for (int rep = 0; rep < 8; rep++) {
            int gid = rep * 256 + tid;
            int c = gid >> 9, rem = gid & 511;
            int row = rem >> 3, seg = rem & 7;
            CP16(st + c * 8192 + SWZ(row * 128 + seg * 16),
                 b0 + (size_t)row * 128 + c * 32 + seg * 4);
        }
    };
    auto loadV = [&](uint32_t st, int t) {
        const float* b0 = Vtg + (size_t)t * 64;
#pragma unroll
        for (int rep = 0; rep < 8; rep++) {
            int gid = rep * 256 + tid;
            int c = gid >> 10, rem = gid & 1023;
            int row = rem >> 3, seg = rem & 7;
            CP16(st + c * 16384 + SWZ(row * 128 + seg * 16),
                 b0 + (size_t)row * S_ + c * 32 + seg * 4);
        }
    };
    loadK(kst0, 0); CPCOMMIT();
    loadK(kst1, 1); CPCOMMIT();
    loadV(vst0, 0); CPCOMMIT();
    CPWAIT2(); __syncthreads();
    if (wid == 0 && elect1()) {
        FPA();
        issueS(tS0, qb, kst0);
        TCOMMIT(mbb + 0);
    }

    float l = 0.f;
    int sph0 = 0, sph1 = 0, pvph = 0;

    for (int t = 0; t < T; t++) {
        const int buf = t & 1;
        if (buf == 0) { MBWAIT(mbb + 0, sph0); sph0 ^= 1; }
        else          { MBWAIT(mbb + 8, sph1); sph1 ^= 1; }
        if (t + 2 < T) loadK(buf ? kst1 : kst0, t + 2);
        CPCOMMIT();
        TFENCE_AFTER();
        uint32_t sr[32];
        TLD32X32(sr, (buf ? tS1 : tS0) + wco);
        TWAITLD();
        TFENCE_BEFORE();
        CPWAIT2(); __syncthreads();
        if (t + 1 < T && wid == 0 && elect1()) {
            FPA();
            issueS(buf ? tS0 : tS1, qb, ((t + 1) & 1) ? kst1 : kst0);
            TCOMMIT(mbb + 8 * ((t + 1) & 1));
        }
        const int lim = q0 + rloc - 64 * t - wco;
        float pf[32];
#pragma unroll
        for (int c = 0; c < 32; c++) {
            float e = (c <= lim) ? ex2f(__uint_as_float(sr[c])) : 0.f;
            l += e;
            pf[c] = tf32r(e);
        }
        if (t > 0) { MBWAIT(mbb + 16, pvph); pvph ^= 1; }
        if (t + 1 < T) loadV(((t + 1) & 1) ? vst1 : vst0, t + 1);
        CPCOMMIT();
        CPWAIT2();
#pragma unroll
        for (int seg = 0; seg < 8; seg++) {
            float4 w4 = {pf[seg * 4 + 0], pf[seg * 4 + 1],
                         pf[seg * 4 + 2], pf[seg * 4 + 3]};
            *(float4*)(pgen + hc * 16384 + SWZ(rloc * 128 + seg * 16)) = w4;
        }
        __syncthreads();
        if (wid == 0 && elect1()) {
            FPA();
            issuePV(tO, pb, buf ? vst1 : vst0, t == 0);
            TCOMMIT(mbb + 16);
        }
    }
    lsh[tid] = l;
    MBWAIT(mbb + 16, pvph);
    TFENCE_AFTER();
    __syncthreads();
    const float inv = 1.f / (lsh[tid] + lsh[tid ^ 128]);
    uint32_t orr[64];
    TLD32X32(orr,      tO + hc * 64);
    TLD32X32(orr + 32, tO + hc * 64 + 32);
    TWAITLD();
    const int b = bh >> 4, h = bh & 15;
    __half* Og = O + ((size_t)(b * S_ + q0 + rloc)) * D_ + h * HD_ + hc * 64;
#pragma unroll
    for (int j = 0; j < 16; j++) {
        __half2 h0 = __floats2half2_rn(__uint_as_float(orr[4 * j + 0]) * inv,
                                       __uint_as_float(orr[4 * j + 1]) * inv);
        __half2 h1 = __floats2half2_rn(__uint_as_float(orr[4 * j + 2]) * inv,
                                       __uint_as_float(orr[4 * j + 3]) * inv);
        uint2 pk = {*(uint32_t*)&h0, *(uint32_t*)&h1};
        *(uint2*)(Og + 4 * j) = pk;
    }
    __syncthreads();
    if (wid == 0) TDEALLOC(tm, 512);
#else
    // -------- naive correct fallback (plain-PTX pass only) --------
    const int bh = blockIdx.y;
    const int qt = (int)gridDim.x - 1 - (int)blockIdx.x;
    const int q0 = qt * 128;
    const int b = bh >> 4, h = bh & 15;
    if (threadIdx.x >= 128) return;
    const int r = q0 + threadIdx.x;
    const float* Qr = Q + ((size_t)bh * S_ + r) * HD_;
    const float* Kb = K + (size_t)bh * S_ * HD_;
    const float* Vb = Vt + (size_t)bh * HD_ * S_;
    float o[HD_];
    for (int c = 0; c < HD_; c++) o[c] = 0.f;
    float l = 0.f;
    for (int kk = 0; kk <= r; kk++) {
        float s = 0.f;
        for (int c = 0; c < HD_; c++) s += Qr[c] * Kb[(size_t)kk * HD_ + c];
        float e = exp2f(s);
        l += e;
        for (int c = 0; c < HD_; c++) o[c] += e * Vb[(size_t)c * S_ + kk];
    }
    const float inv = 1.f / l;
    __half* Og = O + ((size_t)(b * S_ + r)) * D_ + h * HD_;
    for (int c = 0; c < HD_; c++) Og[c] = __float2half(o[c] * inv);
#endif
}

// ---------------------------------------------------------------------------
// Launch
// ---------------------------------------------------------------------------
extern "C" void kernel_launch(void* const* d_in, const int* in_sizes, int n_in,
                              void* d_out, int out_size)
{
    const float* x   = (const float*)d_in[0];
    const float* wq  = (const float*)d_in[1];
    const float* wqb = (const float*)d_in[2];
    const float* wk  = (const float*)d_in[3];
    const float* wkb = (const float*)d_in[4];
    const float* wv  = (const float*)d_in[5];
    const float* wvb = (const float*)d_in[6];
    const float* wo  = (const float*)d_in[7];
    const float* wob = (const float*)d_in[8];
    const float* fc  = (const float*)d_in[9];
    const float* fs  = (const float*)d_in[10];

    float* out   = (float*)d_out;
    float* out_k = out + MAT;
    float* out_v = out_k + MAT;

    float *gq, *gk, *gv, *gqt, *gkr, *gvr;
    __half *gattnh, *gxh, *gwqh, *gwkh, *gwvh, *gwoh;
    cudaGetSymbolAddress((void**)&gq,     g_q);
    cudaGetSymbolAddress((void**)&gk,     g_k);
    cudaGetSymbolAddress((void**)&gv,     g_v);
    cudaGetSymbolAddress((void**)&gqt,    g_qt);
    cudaGetSymbolAddress((void**)&gkr,    g_kr);
    cudaGetSymbolAddress((void**)&gvr,    g_vr);
    cudaGetSymbolAddress((void**)&gattnh, g_attnh);
    cudaGetSymbolAddress((void**)&gxh,    g_xh);
    cudaGetSymbolAddress((void**)&gwqh,   g_wqh);
    cudaGetSymbolAddress((void**)&gwkh,   g_wkh);
    cudaGetSymbolAddress((void**)&gwvh,   g_wvh);
    cudaGetSymbolAddress((void**)&gwoh,   g_woh);

    const int NCONV = (int)((MAT + 4 * WSZ) / 4 / 256);
    conv_fused<<<NCONV, 256>>>(x, wq, wk, wv, wo, gxh, gwqh, gwkh, gwvh, gwoh);

    cudaFuncSetAttribute(gemm_cg2,
                         cudaFuncAttributeMaxDynamicSharedMemorySize, GEMM_SMEM);

    // Fused QKV projection
    gemm_cg2<<<dim3(8, 16, 3), 128, GEMM_SMEM>>>(
        gxh, gwqh, gwkh, gwvh, wqb, wkb, wvb, gq, gk, gv);

    rope_transpose<<<B_ * S_, 256>>>(gq, gk, gv, fc, fs,
                                     gqt, out_k, out_v, gkr, gvr);

    cudaFuncSetAttribute(flash_tc,
                         cudaFuncAttributeMaxDynamicSharedMemorySize, FL_SMEM);
    flash_tc<<<dim3(16, B_ * H_), 256, FL_SMEM>>>(gqt, gkr, gvr, gattnh);

    // O projection
    gemm_cg2<<<dim3(8, 16, 1), 128, GEMM_SMEM>>>(
        gattnh, gwoh, gwoh, gwoh, wob, wob, wob, out, out, out);
}